// round 3
// baseline (speedup 1.0000x reference)
#include <cuda_runtime.h>
#include <math.h>
#include <stdint.h>

#define BB 4
#define SS 4096
#define DD 256
#define UU 64

#define ROWS_PER_BLK 16     // projection kernel
#define MT 128              // query rows per block
#define NT 64               // key tile
#define KST 65              // float2 row stride for Kt2 / Vt2 tiles
#define PST 66              // float row stride for Ps (even -> float2-aligned)

// Scratch for projected Q/K/V (no cudaMalloc allowed)
__device__ float g_q[BB * SS * UU];
__device__ float g_k[BB * SS * UU];
__device__ float g_v[BB * SS * UU];

// ---------------------------------------------------------------------------
// Fused QKV projection (unchanged from round 0 — ~4us, not the bottleneck)
// ---------------------------------------------------------------------------
__global__ __launch_bounds__(192) void proj_kernel(
    const float* __restrict__ x,
    const float* __restrict__ Wq, const float* __restrict__ bq,
    const float* __restrict__ Wk, const float* __restrict__ bk,
    const float* __restrict__ Wv, const float* __restrict__ bv)
{
    __shared__ float xs[ROWS_PER_BLK * DD];

    const int row0 = blockIdx.x * ROWS_PER_BLK;
    const float* xrow = x + (size_t)row0 * DD;

    for (int i = threadIdx.x; i < ROWS_PER_BLK * DD / 4; i += blockDim.x) {
        ((float4*)xs)[i] = ((const float4*)xrow)[i];
    }
    __syncthreads();

    const int mat = threadIdx.x / UU;   // 0=Q 1=K 2=V
    const int u   = threadIdx.x % UU;
    const float* W    = (mat == 0) ? Wq : (mat == 1) ? Wk : Wv;
    const float* bias = (mat == 0) ? bq : (mat == 1) ? bk : bv;
    float*       out  = (mat == 0) ? g_q : (mat == 1) ? g_k : g_v;

    float acc[ROWS_PER_BLK];
    const float b0 = bias[u];
#pragma unroll
    for (int r = 0; r < ROWS_PER_BLK; r++) acc[r] = b0;

#pragma unroll 8
    for (int d = 0; d < DD; d++) {
        const float w = W[d * UU + u];
#pragma unroll
        for (int r = 0; r < ROWS_PER_BLK; r++)
            acc[r] = fmaf(xs[r * DD + d], w, acc[r]);
    }

#pragma unroll
    for (int r = 0; r < ROWS_PER_BLK; r++)
        out[(size_t)(row0 + r) * UU + u] = acc[r];
}

// ---------------------------------------------------------------------------
// tf32 helpers
// ---------------------------------------------------------------------------
__device__ __forceinline__ float ftf32(float x) {
    uint32_t u;
    asm("cvt.rna.tf32.f32 %0, %1;" : "=r"(u) : "f"(x));
    return __uint_as_float(u);
}

// D += A(16x8 tf32) * B(8x8 tf32), fp32 accumulate.
// Lo-parts are passed as raw fp32 bits; HW truncation of their tail adds only
// O(2^-22) relative error.
__device__ __forceinline__ void mma8(float d[4],
                                     float a0, float a1, float a2, float a3,
                                     float b0, float b1)
{
    asm volatile(
        "mma.sync.aligned.m16n8k8.row.col.f32.tf32.tf32.f32 "
        "{%0,%1,%2,%3},{%4,%5,%6,%7},{%8,%9},{%0,%1,%2,%3};\n"
        : "+f"(d[0]), "+f"(d[1]), "+f"(d[2]), "+f"(d[3])
        : "r"(__float_as_uint(a0)), "r"(__float_as_uint(a1)),
          "r"(__float_as_uint(a2)), "r"(__float_as_uint(a3)),
          "r"(__float_as_uint(b0)), "r"(__float_as_uint(b1)));
}

// ---------------------------------------------------------------------------
// Flash attention on tensor cores (3xTF32 compensated).
// 8 warps; warp w owns 16 query rows [16w, 16w+16) x all 64 key cols.
// Q fragments (hi/lo split) live in registers for the whole kernel.
// K tile: transposed, float2(hi,lo).  V tile: natural, float2(hi,lo).
// P: warp-private fp32 smem plane, split hi/lo at A-fragment load.
// Online softmax: rows map to lane quads of the m16n8 C fragment; state in regs.
// ---------------------------------------------------------------------------
__global__ __launch_bounds__(256) void attn_kernel(float* __restrict__ out)
{
    extern __shared__ float smem[];
    float2* Kt2 = (float2*)smem;                 // [UU][KST]   Kt2[u][n] = (hi,lo)
    float2* Vt2 = Kt2 + UU * KST;                // [NT][KST]   Vt2[n][u] = (hi,lo)
    float*  Ps  = (float*)(Vt2 + NT * KST);      // [MT][PST]   P, fp32

    const int b   = blockIdx.x / (SS / MT);
    const int mt  = blockIdx.x % (SS / MT);
    const int tid = threadIdx.x;
    const int w    = tid >> 5;
    const int lane = tid & 31;
    const int g = lane >> 2;       // group id  (row within 8)
    const int q = lane & 3;        // thread-in-group (col / k index)
    const int r0 = w * 16 + g;     // block-local row for a0/c0 (r0+8 for a1/c2)

    const size_t rowbase = (size_t)b * SS + (size_t)mt * MT;
    const float* kg = g_k + (size_t)b * SS * UU;
    const float* vg = g_v + (size_t)b * SS * UU;

    // ---- Q fragments: load once, fold 1/sqrt(64), split hi/lo ----
    float qh[8][4], ql[8][4];
    {
        const float* qg = g_q + rowbase * UU;
#pragma unroll
        for (int k = 0; k < 8; k++) {
            float v0 = qg[(size_t)(r0)     * UU + 8 * k + q]     * 0.125f;
            float v1 = qg[(size_t)(r0 + 8) * UU + 8 * k + q]     * 0.125f;
            float v2 = qg[(size_t)(r0)     * UU + 8 * k + q + 4] * 0.125f;
            float v3 = qg[(size_t)(r0 + 8) * UU + 8 * k + q + 4] * 0.125f;
            qh[k][0] = ftf32(v0); ql[k][0] = v0 - qh[k][0];
            qh[k][1] = ftf32(v1); ql[k][1] = v1 - qh[k][1];
            qh[k][2] = ftf32(v2); ql[k][2] = v2 - qh[k][2];
            qh[k][3] = ftf32(v3); ql[k][3] = v3 - qh[k][3];
        }
    }

    float Of[8][4];
#pragma unroll
    for (int j = 0; j < 8; j++)
#pragma unroll
        for (int i = 0; i < 4; i++) Of[j][i] = 0.f;
    float m0r = -1e30f, m1r = -1e30f, l0r = 0.f, l1r = 0.f;

    for (int nt = 0; nt < SS / NT; nt++) {
        __syncthreads();   // tiles (and Ps) from previous iteration fully consumed

        // ---- cooperative K/V tile load + tf32 hi/lo split ----
        {
            const float* kp = kg + (size_t)nt * NT * UU;
            for (int i = tid; i < NT * (UU / 4); i += 256) {
                const int n  = i >> 4;           // key index 0..63
                const int u4 = (i & 15) * 4;     // u 0..60 step 4
                float4 kv = *(const float4*)(kp + n * UU + u4);
                float h;
                h = ftf32(kv.x); Kt2[(u4 + 0) * KST + n] = make_float2(h, kv.x - h);
                h = ftf32(kv.y); Kt2[(u4 + 1) * KST + n] = make_float2(h, kv.y - h);
                h = ftf32(kv.z); Kt2[(u4 + 2) * KST + n] = make_float2(h, kv.z - h);
                h = ftf32(kv.w); Kt2[(u4 + 3) * KST + n] = make_float2(h, kv.w - h);
            }
            const float* vp = vg + (size_t)nt * NT * UU;
            for (int i = tid; i < NT * (UU / 4); i += 256) {
                const int n  = i >> 4;
                const int u4 = (i & 15) * 4;
                float4 vv = *(const float4*)(vp + n * UU + u4);
                float h;
                h = ftf32(vv.x); Vt2[n * KST + u4 + 0] = make_float2(h, vv.x - h);
                h = ftf32(vv.y); Vt2[n * KST + u4 + 1] = make_float2(h, vv.y - h);
                h = ftf32(vv.z); Vt2[n * KST + u4 + 2] = make_float2(h, vv.z - h);
                h = ftf32(vv.w); Vt2[n * KST + u4 + 3] = make_float2(h, vv.w - h);
            }
        }
        __syncthreads();

        // ---- S = Q K^T (3xTF32) ----
        float Sf[8][4];
#pragma unroll
        for (int j = 0; j < 8; j++) {
            Sf[j][0] = Sf[j][1] = Sf[j][2] = Sf[j][3] = 0.f;
#pragma unroll
            for (int k = 0; k < 8; k++) {
                const float2 kb0 = Kt2[(8 * k + q)     * KST + 8 * j + g];
                const float2 kb1 = Kt2[(8 * k + q + 4) * KST + 8 * j + g];
                mma8(Sf[j], qh[k][0], qh[k][1], qh[k][2], qh[k][3], kb0.x, kb1.x);
                mma8(Sf[j], qh[k][0], qh[k][1], qh[k][2], qh[k][3], kb0.y, kb1.y);
                mma8(Sf[j], ql[k][0], ql[k][1], ql[k][2], ql[k][3], kb0.x, kb1.x);
            }
        }

        // ---- online softmax: row r0 <-> (c0,c1), row r0+8 <-> (c2,c3) ----
        float rm0 = -1e30f, rm1 = -1e30f;
#pragma unroll
        for (int j = 0; j < 8; j++) {
            rm0 = fmaxf(rm0, fmaxf(Sf[j][0], Sf[j][1]));
            rm1 = fmaxf(rm1, fmaxf(Sf[j][2], Sf[j][3]));
        }
        rm0 = fmaxf(rm0, __shfl_xor_sync(0xffffffffu, rm0, 1));
        rm0 = fmaxf(rm0, __shfl_xor_sync(0xffffffffu, rm0, 2));
        rm1 = fmaxf(rm1, __shfl_xor_sync(0xffffffffu, rm1, 1));
        rm1 = fmaxf(rm1, __shfl_xor_sync(0xffffffffu, rm1, 2));

        const float mn0 = fmaxf(m0r, rm0);
        const float mn1 = fmaxf(m1r, rm1);
        const float c0  = __expf(m0r - mn0);
        const float c1  = __expf(m1r - mn1);
        m0r = mn0; m1r = mn1;

        float rs0 = 0.f, rs1 = 0.f;
#pragma unroll
        for (int j = 0; j < 8; j++) {
            Sf[j][0] = __expf(Sf[j][0] - mn0); rs0 += Sf[j][0];
            Sf[j][1] = __expf(Sf[j][1] - mn0); rs0 += Sf[j][1];
            Sf[j][2] = __expf(Sf[j][2] - mn1); rs1 += Sf[j][2];
            Sf[j][3] = __expf(Sf[j][3] - mn1); rs1 += Sf[j][3];
        }
        rs0 += __shfl_xor_sync(0xffffffffu, rs0, 1);
        rs0 += __shfl_xor_sync(0xffffffffu, rs0, 2);
        rs1 += __shfl_xor_sync(0xffffffffu, rs1, 1);
        rs1 += __shfl_xor_sync(0xffffffffu, rs1, 2);

        l0r = l0r * c0 + rs0;
        l1r = l1r * c1 + rs1;
#pragma unroll
        for (int j = 0; j < 8; j++) {
            Of[j][0] *= c0; Of[j][1] *= c0;
            Of[j][2] *= c1; Of[j][3] *= c1;
        }

        // ---- stash P (warp-private rows; fp32) ----
#pragma unroll
        for (int j = 0; j < 8; j++) {
            *(float2*)&Ps[(r0)     * PST + 8 * j + 2 * q] = make_float2(Sf[j][0], Sf[j][1]);
            *(float2*)&Ps[(r0 + 8) * PST + 8 * j + 2 * q] = make_float2(Sf[j][2], Sf[j][3]);
        }
        __syncwarp();

        // ---- O += P V (3xTF32) ----
#pragma unroll
        for (int kk = 0; kk < 8; kk++) {
            const float p0 = Ps[(r0)     * PST + 8 * kk + q];
            const float p1 = Ps[(r0 + 8) * PST + 8 * kk + q];
            const float p2 = Ps[(r0)     * PST + 8 * kk + q + 4];
            const float p3 = Ps[(r0 + 8) * PST + 8 * kk + q + 4];
            const float ah0 = ftf32(p0), al0 = p0 - ah0;
            const float ah1 = ftf32(p1), al1 = p1 - ah1;
            const float ah2 = ftf32(p2), al2 = p2 - ah2;
            const float ah3 = ftf32(p3), al3 = p3 - ah3;
#pragma unroll
            for (int j = 0; j < 8; j++) {
                const float2 vb0 = Vt2[(8 * kk + q)     * KST + 8 * j + g];
                const float2 vb1 = Vt2[(8 * kk + q + 4) * KST + 8 * j + g];
                mma8(Of[j], ah0, ah1, ah2, ah3, vb0.x, vb1.x);
                mma8(Of[j], ah0, ah1, ah2, ah3, vb0.y, vb1.y);
                mma8(Of[j], al0, al1, al2, al3, vb0.x, vb1.x);
            }
        }
    }

    // ---- epilogue: normalize and store ----
    float* op = out + rowbase * UU;
    const float inv0 = 1.f / l0r;
    const float inv1 = 1.f / l1r;
#pragma unroll
    for (int j = 0; j < 8; j++) {
        *(float2*)(op + (size_t)(r0)     * UU + 8 * j + 2 * q) =
            make_float2(Of[j][0] * inv0, Of[j][1] * inv0);
        *(float2*)(op + (size_t)(r0 + 8) * UU + 8 * j + 2 * q) =
            make_float2(Of[j][2] * inv1, Of[j][3] * inv1);
    }
}

// ---------------------------------------------------------------------------
extern "C" void kernel_launch(void* const* d_in, const int* in_sizes, int n_in,
                              void* d_out, int out_size)
{
    const float* x  = (const float*)d_in[0];
    const float* Wq = (const float*)d_in[1];
    const float* bq = (const float*)d_in[2];
    const float* Wk = (const float*)d_in[3];
    const float* bk = (const float*)d_in[4];
    const float* Wv = (const float*)d_in[5];
    const float* bv = (const float*)d_in[6];
    float* out = (float*)d_out;

    proj_kernel<<<(BB * SS) / ROWS_PER_BLK, 192>>>(x, Wq, bq, Wk, bk, Wv, bv);

    const int smem_bytes = (UU * KST + NT * KST) * (int)sizeof(float2)
                         + MT * PST * (int)sizeof(float);           // 100,352 B
    cudaFuncSetAttribute(attn_kernel, cudaFuncAttributeMaxDynamicSharedMemorySize,
                         smem_bytes);
    attn_kernel<<<BB * (SS / MT), 256, smem_bytes>>>(out);
}

// round 4
// speedup vs baseline: 3.5119x; 3.5119x over previous
#include <cuda_runtime.h>
#include <cuda_bf16.h>
#include <math.h>
#include <stdint.h>

#define BB 4
#define SS 4096
#define DD 256
#define UU 64

#define ROWS_PER_BLK 16     // projection kernel
#define MT 64               // query rows per attention block
#define NTILES (SS / 64)

// Scratch (no cudaMalloc allowed)
__device__ float          g_q [BB * SS * UU];                 // fp32, [b][s][u]
__device__ __nv_bfloat16  g_kh[BB * UU * SS];                 // K hi, TRANSPOSED [b][u][s]
__device__ __nv_bfloat16  g_kl[BB * UU * SS];                 // K lo
__device__ __nv_bfloat16  g_vh[BB * SS * UU];                 // V hi, natural [b][s][u]
__device__ __nv_bfloat16  g_vl[BB * SS * UU];                 // V lo

// ---------------------------------------------------------------------------
// Fused QKV projection. Q stays fp32; K/V are emitted as bf16 hi/lo planes
// (x = hi + lo, each bf16) so the attention kernel reads bf16 directly.
// K is written transposed ([u][s]) — each thread holds 16 consecutive s for
// its u, so the transposed store is two 16B stores per plane.
// ---------------------------------------------------------------------------
__global__ __launch_bounds__(192) void proj_kernel(
    const float* __restrict__ x,
    const float* __restrict__ Wq, const float* __restrict__ bq,
    const float* __restrict__ Wk, const float* __restrict__ bk,
    const float* __restrict__ Wv, const float* __restrict__ bv)
{
    __shared__ float xs[ROWS_PER_BLK * DD];

    const int row0 = blockIdx.x * ROWS_PER_BLK;
    const float* xrow = x + (size_t)row0 * DD;

    for (int i = threadIdx.x; i < ROWS_PER_BLK * DD / 4; i += blockDim.x)
        ((float4*)xs)[i] = ((const float4*)xrow)[i];
    __syncthreads();

    const int mat = threadIdx.x / UU;   // 0=Q 1=K 2=V
    const int u   = threadIdx.x % UU;
    const float* W    = (mat == 0) ? Wq : (mat == 1) ? Wk : Wv;
    const float* bias = (mat == 0) ? bq : (mat == 1) ? bk : bv;

    float acc[ROWS_PER_BLK];
    const float b0 = bias[u];
#pragma unroll
    for (int r = 0; r < ROWS_PER_BLK; r++) acc[r] = b0;

#pragma unroll 8
    for (int d = 0; d < DD; d++) {
        const float w = W[d * UU + u];
#pragma unroll
        for (int r = 0; r < ROWS_PER_BLK; r++)
            acc[r] = fmaf(xs[r * DD + d], w, acc[r]);
    }

    if (mat == 0) {
#pragma unroll
        for (int r = 0; r < ROWS_PER_BLK; r++)
            g_q[(size_t)(row0 + r) * UU + u] = acc[r];
    } else {
        __align__(16) __nv_bfloat16 hb[ROWS_PER_BLK];
        __align__(16) __nv_bfloat16 lb[ROWS_PER_BLK];
#pragma unroll
        for (int r = 0; r < ROWS_PER_BLK; r++) {
            const float a = acc[r];
            const __nv_bfloat16 h = __float2bfloat16(a);
            hb[r] = h;
            lb[r] = __float2bfloat16(a - __bfloat162float(h));
        }
        if (mat == 1) {
            const int b  = row0 / SS;
            const int s0 = row0 % SS;
            const size_t off = ((size_t)b * UU + u) * SS + s0;
            *(uint4*)(g_kh + off)     = ((const uint4*)hb)[0];
            *(uint4*)(g_kh + off + 8) = ((const uint4*)hb)[1];
            *(uint4*)(g_kl + off)     = ((const uint4*)lb)[0];
            *(uint4*)(g_kl + off + 8) = ((const uint4*)lb)[1];
        } else {
#pragma unroll
            for (int r = 0; r < ROWS_PER_BLK; r++) {
                g_vh[(size_t)(row0 + r) * UU + u] = hb[r];
                g_vl[(size_t)(row0 + r) * UU + u] = lb[r];
            }
        }
    }
}

// ---------------------------------------------------------------------------
// mma / ldmatrix helpers
// ---------------------------------------------------------------------------
__device__ __forceinline__ void ldsm2t(uint32_t& r0, uint32_t& r1, uint32_t addr)
{
    asm volatile("ldmatrix.sync.aligned.m8n8.x2.trans.shared.b16 {%0,%1},[%2];"
                 : "=r"(r0), "=r"(r1) : "r"(addr));
}

__device__ __forceinline__ void mma16(float d[4],
                                      uint32_t a0, uint32_t a1, uint32_t a2, uint32_t a3,
                                      uint32_t b0, uint32_t b1)
{
    asm volatile(
        "mma.sync.aligned.m16n8k16.row.col.f32.bf16.bf16.f32 "
        "{%0,%1,%2,%3},{%4,%5,%6,%7},{%8,%9},{%0,%1,%2,%3};\n"
        : "+f"(d[0]), "+f"(d[1]), "+f"(d[2]), "+f"(d[3])
        : "r"(a0), "r"(a1), "r"(a2), "r"(a3), "r"(b0), "r"(b1));
}

// split (x,y) into packed bf16x2 hi (returned) and lo (out-param)
__device__ __forceinline__ uint32_t bsplit(float x, float y, uint32_t& lo)
{
    __nv_bfloat162 h2 = __floats2bfloat162_rn(x, y);
    const float rx = x - __bfloat162float(h2.x);
    const float ry = y - __bfloat162float(h2.y);
    __nv_bfloat162 l2 = __floats2bfloat162_rn(rx, ry);
    lo = *(uint32_t*)&l2;
    return *(uint32_t*)&h2;
}

// ---------------------------------------------------------------------------
// Flash attention, bf16 tensor cores with 3-term compensation (hh+hl+lh).
// 128 threads = 4 warps; warp w owns rows [16w,16w+16) of a 64-row Q block.
// Q fragments (hi/lo, packed bf16x2) live in registers for the whole kernel.
// K tile smem: [u][key] bf16, XOR-swizzled; V tile: [key][u] bf16, swizzled.
// B fragments via ldmatrix.x2.trans (conflict-free). P = S fragment remap in
// registers (no smem). Online softmax state in registers.
// ---------------------------------------------------------------------------
__global__ __launch_bounds__(128, 3) void attn_kernel(float* __restrict__ out)
{
    __shared__ __align__(16) __nv_bfloat16 KH[UU * 64];
    __shared__ __align__(16) __nv_bfloat16 KL[UU * 64];
    __shared__ __align__(16) __nv_bfloat16 VH[64 * UU];
    __shared__ __align__(16) __nv_bfloat16 VL[64 * UU];

    const int b    = blockIdx.x >> 6;    // SS/MT = 64 blocks per batch
    const int mt   = blockIdx.x & 63;
    const int tid  = threadIdx.x;
    const int w    = tid >> 5;
    const int lane = tid & 31;
    const int g    = lane >> 2;
    const int q    = lane & 3;
    const int r0   = w * 16 + g;         // block-local row (r0+8 = sibling)
    const int lr   = lane & 15;          // ldmatrix row provider index

    // ---- Q fragments: load, fold 1/sqrt(64), hi/lo split, pack ----
    uint32_t qh[4][4], ql[4][4];
    {
        const float* qg = g_q + ((size_t)b * SS + mt * MT) * UU;
#pragma unroll
        for (int t = 0; t < 4; t++) {
            float2 x0 = *(const float2*)(qg + (size_t)(r0)     * UU + 16 * t + 2 * q);
            float2 x1 = *(const float2*)(qg + (size_t)(r0 + 8) * UU + 16 * t + 2 * q);
            float2 x2 = *(const float2*)(qg + (size_t)(r0)     * UU + 16 * t + 8 + 2 * q);
            float2 x3 = *(const float2*)(qg + (size_t)(r0 + 8) * UU + 16 * t + 8 + 2 * q);
            qh[t][0] = bsplit(x0.x * 0.125f, x0.y * 0.125f, ql[t][0]);
            qh[t][1] = bsplit(x1.x * 0.125f, x1.y * 0.125f, ql[t][1]);
            qh[t][2] = bsplit(x2.x * 0.125f, x2.y * 0.125f, ql[t][2]);
            qh[t][3] = bsplit(x3.x * 0.125f, x3.y * 0.125f, ql[t][3]);
        }
    }

    float Of[8][4];
#pragma unroll
    for (int j = 0; j < 8; j++)
#pragma unroll
        for (int i = 0; i < 4; i++) Of[j][i] = 0.f;
    float m0 = -1e30f, m1 = -1e30f, l0 = 0.f, l1 = 0.f;

    const __nv_bfloat16* khg = g_kh + (size_t)b * UU * SS;
    const __nv_bfloat16* klg = g_kl + (size_t)b * UU * SS;
    const __nv_bfloat16* vhg = g_vh + (size_t)b * SS * UU;
    const __nv_bfloat16* vlg = g_vl + (size_t)b * SS * UU;

    for (int nt = 0; nt < NTILES; nt++) {
        __syncthreads();  // previous tile fully consumed

        // ---- cooperative tile load: 16B chunks, XOR swizzle on store ----
#pragma unroll
        for (int i0 = 0; i0 < 4; i0++) {
            const int i   = tid + i0 * 128;
            const int row = i >> 3;
            const int c   = i & 7;
            const int sw  = row * 64 + ((c ^ (row & 7)) * 8);
            *(uint4*)&KH[sw] = *(const uint4*)(khg + (size_t)row * SS + nt * 64 + c * 8);
            *(uint4*)&KL[sw] = *(const uint4*)(klg + (size_t)row * SS + nt * 64 + c * 8);
            *(uint4*)&VH[sw] = *(const uint4*)(vhg + (size_t)(nt * 64 + row) * UU + c * 8);
            *(uint4*)&VL[sw] = *(const uint4*)(vlg + (size_t)(nt * 64 + row) * UU + c * 8);
        }
        __syncthreads();

        // ---- S = Q K^T ----
        float Sf[8][4];
#pragma unroll
        for (int j = 0; j < 8; j++) {
            Sf[j][0] = Sf[j][1] = Sf[j][2] = Sf[j][3] = 0.f;
#pragma unroll
            for (int t = 0; t < 4; t++) {
                const int r = 16 * t + lr;
                const int sw = r * 64 + ((j ^ (r & 7)) * 8);
                uint32_t bh0, bh1, bl0, bl1;
                ldsm2t(bh0, bh1, (uint32_t)__cvta_generic_to_shared(&KH[sw]));
                ldsm2t(bl0, bl1, (uint32_t)__cvta_generic_to_shared(&KL[sw]));
                mma16(Sf[j], qh[t][0], qh[t][1], qh[t][2], qh[t][3], bh0, bh1);
                mma16(Sf[j], qh[t][0], qh[t][1], qh[t][2], qh[t][3], bl0, bl1);
                mma16(Sf[j], ql[t][0], ql[t][1], ql[t][2], ql[t][3], bh0, bh1);
            }
        }

        // ---- online softmax: row r0 <-> (c0,c1), row r0+8 <-> (c2,c3) ----
        float rm0 = -1e30f, rm1 = -1e30f;
#pragma unroll
        for (int j = 0; j < 8; j++) {
            rm0 = fmaxf(rm0, fmaxf(Sf[j][0], Sf[j][1]));
            rm1 = fmaxf(rm1, fmaxf(Sf[j][2], Sf[j][3]));
        }
        rm0 = fmaxf(rm0, __shfl_xor_sync(0xffffffffu, rm0, 1));
        rm0 = fmaxf(rm0, __shfl_xor_sync(0xffffffffu, rm0, 2));
        rm1 = fmaxf(rm1, __shfl_xor_sync(0xffffffffu, rm1, 1));
        rm1 = fmaxf(rm1, __shfl_xor_sync(0xffffffffu, rm1, 2));

        const float mn0 = fmaxf(m0, rm0);
        const float mn1 = fmaxf(m1, rm1);
        const float c0  = __expf(m0 - mn0);
        const float c1  = __expf(m1 - mn1);
        m0 = mn0; m1 = mn1;

        float rs0 = 0.f, rs1 = 0.f;
#pragma unroll
        for (int j = 0; j < 8; j++) {
            Sf[j][0] = __expf(Sf[j][0] - mn0); rs0 += Sf[j][0];
            Sf[j][1] = __expf(Sf[j][1] - mn0); rs0 += Sf[j][1];
            Sf[j][2] = __expf(Sf[j][2] - mn1); rs1 += Sf[j][2];
            Sf[j][3] = __expf(Sf[j][3] - mn1); rs1 += Sf[j][3];
        }
        rs0 += __shfl_xor_sync(0xffffffffu, rs0, 1);
        rs0 += __shfl_xor_sync(0xffffffffu, rs0, 2);
        rs1 += __shfl_xor_sync(0xffffffffu, rs1, 1);
        rs1 += __shfl_xor_sync(0xffffffffu, rs1, 2);

        l0 = l0 * c0 + rs0;
        l1 = l1 * c1 + rs1;
#pragma unroll
        for (int j = 0; j < 8; j++) {
            Of[j][0] *= c0; Of[j][1] *= c0;
            Of[j][2] *= c1; Of[j][3] *= c1;
        }

        // ---- P: C-fragment -> A-fragment remap in registers (no smem) ----
        uint32_t ph01[8], ph23[8], pl01[8], pl23[8];
#pragma unroll
        for (int j = 0; j < 8; j++) {
            ph01[j] = bsplit(Sf[j][0], Sf[j][1], pl01[j]);
            ph23[j] = bsplit(Sf[j][2], Sf[j][3], pl23[j]);
        }

        // ---- O += P V ----
#pragma unroll
        for (int j = 0; j < 8; j++) {      // u-chunk
#pragma unroll
            for (int t = 0; t < 4; t++) {  // key-chunk
                const int r = 16 * t + lr;
                const int sw = r * 64 + ((j ^ (r & 7)) * 8);
                uint32_t vh0, vh1, vl0, vl1;
                ldsm2t(vh0, vh1, (uint32_t)__cvta_generic_to_shared(&VH[sw]));
                ldsm2t(vl0, vl1, (uint32_t)__cvta_generic_to_shared(&VL[sw]));
                mma16(Of[j], ph01[2*t], ph23[2*t], ph01[2*t+1], ph23[2*t+1], vh0, vh1);
                mma16(Of[j], ph01[2*t], ph23[2*t], ph01[2*t+1], ph23[2*t+1], vl0, vl1);
                mma16(Of[j], pl01[2*t], pl23[2*t], pl01[2*t+1], pl23[2*t+1], vh0, vh1);
            }
        }
    }

    // ---- epilogue: normalize and store ----
    float* op = out + ((size_t)b * SS + mt * MT) * UU;
    const float inv0 = 1.f / l0;
    const float inv1 = 1.f / l1;
#pragma unroll
    for (int j = 0; j < 8; j++) {
        *(float2*)(op + (size_t)(r0)     * UU + 8 * j + 2 * q) =
            make_float2(Of[j][0] * inv0, Of[j][1] * inv0);
        *(float2*)(op + (size_t)(r0 + 8) * UU + 8 * j + 2 * q) =
            make_float2(Of[j][2] * inv1, Of[j][3] * inv1);
    }
}

// ---------------------------------------------------------------------------
extern "C" void kernel_launch(void* const* d_in, const int* in_sizes, int n_in,
                              void* d_out, int out_size)
{
    const float* x  = (const float*)d_in[0];
    const float* Wq = (const float*)d_in[1];
    const float* bq = (const float*)d_in[2];
    const float* Wk = (const float*)d_in[3];
    const float* bk = (const float*)d_in[4];
    const float* Wv = (const float*)d_in[5];
    const float* bv = (const float*)d_in[6];
    float* out = (float*)d_out;

    proj_kernel<<<(BB * SS) / ROWS_PER_BLK, 192>>>(x, Wq, bq, Wk, bk, Wv, bv);
    attn_kernel<<<BB * (SS / MT), 128>>>(out);
}